// round 1
// baseline (speedup 1.0000x reference)
#include <cuda_runtime.h>
#include <cstdint>

#define MUL0   64
#define MUL1   32
#define DIM    160
#define NPAIR0 2016
#define KTOT   2608
#define KPAD   2624
#define KC     64
#define NCHUNK (KPAD / KC)   // 41
#define TN     64            // nodes per block
#define THREADS 256

// ---------------- device scratch (no allocations allowed) ----------------
__device__ float    g_Wc[KPAD * 64];        // combined out0 weights, scaled, padded
__device__ float    g_W3p[32 * 64 * 32];    // W3 * C1 * inv_sqrt3
__device__ unsigned g_kmap[KPAD];           // k -> u | v<<8 | type<<16

// ---------------- small PTX helpers ----------------
__device__ __forceinline__ void cp_async16(uint32_t saddr, const void* gptr) {
    asm volatile("cp.async.cg.shared.global [%0], [%1], 16;\n" :: "r"(saddr), "l"(gptr));
}
__device__ __forceinline__ void cp_commit() { asm volatile("cp.async.commit_group;\n" ::: "memory"); }
template<int N> __device__ __forceinline__ void cp_wait() {
    asm volatile("cp.async.wait_group %0;\n" :: "n"(N) : "memory");
}
__device__ __forceinline__ unsigned long long ffma2(unsigned long long a, unsigned long long b,
                                                    unsigned long long c) {
    unsigned long long d;
    asm("fma.rn.f32x2 %0, %1, %2, %3;" : "=l"(d) : "l"(a), "l"(b), "l"(c));
    return d;
}
__device__ __forceinline__ unsigned long long pack2(float x, float y) {
    unsigned long long d;
    asm("mov.b64 %0, {%1, %2};" : "=l"(d) : "f"(x), "f"(y));
    return d;
}
__device__ __forceinline__ float2 unpack2(unsigned long long a) {
    float2 r; asm("mov.b64 {%0, %1}, %2;" : "=f"(r.x), "=f"(r.y) : "l"(a)); return r;
}

// ---------------- prep: pack weights + pair table ----------------
__global__ void prep_kernel(const float* __restrict__ W1, const float* __restrict__ W2,
                            const float* __restrict__ W3, const float* __restrict__ W4,
                            const float* __restrict__ W5) {
    const float C0   = sqrtf(1.0f / 2608.0f);
    const float INV3 = 0.5773502691896258f;
    const float C0I  = C0 * INV3;
    const float C1I  = sqrtf(1.0f / 2048.0f);   // C1 * inv_sqrt3

    int t = blockIdx.x * blockDim.x + threadIdx.x;
    int stride = gridDim.x * blockDim.x;

    if (t < 64 * 64) {
        int u = t >> 6, v = t & 63;
        if (u < v)  g_kmap[u * 63 - (u * (u - 1)) / 2 + (v - u - 1)] = (unsigned)(u | (v << 8));
        if (u == v) g_kmap[NPAIR0 + u] = (unsigned)(u | (u << 8));
        if (u < 32 && v < 32) {
            if (u < v)  g_kmap[2080 + u * 31 - (u * (u - 1)) / 2 + (v - u - 1)] =
                            (unsigned)(u | (v << 8) | 0x10000);
            if (u == v) g_kmap[2576 + u] = (unsigned)(u | (u << 8) | 0x10000);
        }
    }
    if (t < KPAD - KTOT) g_kmap[KTOT + t] = 0u;

    for (int idx = t; idx < KPAD * 64; idx += stride) {
        int k = idx >> 6, w = idx & 63;
        float val = 0.f;
        if (k < NPAIR0)      val = C0  * W1[idx];
        else if (k < 2080)   val = C0  * W2[(k - 2016) * 64 + w];
        else if (k < 2576)   val = C0I * W4[(k - 2080) * 64 + w];
        else if (k < KTOT)   val = C0I * W5[(k - 2576) * 64 + w];
        g_Wc[idx] = val;
    }
    for (int idx = t; idx < 32 * 64 * 32; idx += stride)
        g_W3p[idx] = C1I * W3[idx];
}

// ---------------- main fused kernel ----------------
// dynamic smem layout (floats):
#define WS_OFF   0                   // Ws   [2][64][64]  = 8192 floats (32KB), aliased by W3 chunks
#define FSD_OFF  8192                // FsD  [64][132]    = 8448 floats (duplicated features)
#define XS0_OFF  (8192 + 8448)       // xs0  [64][64]
#define XS1_OFF  (XS0_OFF + 4096)    // xs1  [3][32][64]
#define SMEM_FLOATS (XS1_OFF + 6144) // 26880 floats
#define SMEM_BYTES  (SMEM_FLOATS * 4) // 107520 B

__global__ void __launch_bounds__(THREADS, 2)
node_block_kernel(const float* __restrict__ A, const float* __restrict__ B,
                  float* __restrict__ out, int nNodes) {
    extern __shared__ float sm[];
    float* Ws  = sm + WS_OFF;
    float* FsD = sm + FSD_OFF;
    float* xs0 = sm + XS0_OFF;
    float* xs1 = sm + XS1_OFF;

    const int t = threadIdx.x;
    const int nbase = blockIdx.x * TN;
    const uint32_t ws_s = (uint32_t)__cvta_generic_to_shared(Ws);

    // prefetch Wc chunk 0 into buf0 (independent of x load)
    {
        const char* gsrc = (const char*)g_Wc;
        #pragma unroll
        for (int j = 0; j < 4; ++j) {
            int e = t + THREADS * j;
            cp_async16(ws_s + e * 16, gsrc + e * 16);
        }
        cp_commit();
    }

    // load x = A + B, scatter transposed into smem
    for (int e = t; e < TN * DIM; e += THREADS) {
        int n = e / DIM, d = e - n * DIM;
        int gn = nbase + n;
        float v = 0.f;
        if (gn < nNodes) v = A[(size_t)gn * DIM + d] + B[(size_t)gn * DIM + d];
        if (d < MUL0) xs0[d * TN + n] = v;
        else {
            int dd = d - MUL0; int u = dd / 3, i = dd - 3 * u;
            xs1[(i * MUL1 + u) * TN + n] = v;
        }
    }
    __syncthreads();

    // ---------------- phase 1: out0 = F(x) @ Wc  (K = 2624 padded) ----------------
    const int ti = t >> 4;   // node quad: rows 4*ti .. 4*ti+3
    const int tj = t & 15;   // w quad:    cols 4*tj .. 4*tj+3
    unsigned long long acc[4][2];
    #pragma unroll
    for (int r = 0; r < 4; ++r) { acc[r][0] = 0ull; acc[r][1] = 0ull; }

    const int nF  = t & 63;  // feature node
    const int kkB = t >> 6;  // feature kk base (0..3)

    for (int c = 0; c < NCHUNK; ++c) {
        // generate features for this K-chunk (duplicated for f32x2 operands)
        const int kb = c * KC;
        #pragma unroll
        for (int j = 0; j < 16; ++j) {
            int kk = kkB + 4 * j;
            unsigned km = g_kmap[kb + kk];
            int u = km & 255, v = (km >> 8) & 255;
            float val;
            if (km & 0x10000u) {
                val = xs1[(0 * MUL1 + u) * TN + nF] * xs1[(0 * MUL1 + v) * TN + nF]
                    + xs1[(1 * MUL1 + u) * TN + nF] * xs1[(1 * MUL1 + v) * TN + nF]
                    + xs1[(2 * MUL1 + u) * TN + nF] * xs1[(2 * MUL1 + v) * TN + nF];
            } else {
                val = xs0[u * TN + nF] * xs0[v * TN + nF];
            }
            *(float2*)&FsD[kk * 132 + 2 * nF] = make_float2(val, val);
        }

        // prefetch next weight chunk into the other buffer
        if (c + 1 < NCHUNK) {
            const char* gsrc = (const char*)(g_Wc + (c + 1) * KC * 64);
            uint32_t dst = ws_s + ((c + 1) & 1) * 16384;
            #pragma unroll
            for (int j = 0; j < 4; ++j) {
                int e = t + THREADS * j;
                cp_async16(dst + e * 16, gsrc + e * 16);
            }
            cp_commit();
            cp_wait<1>();
        } else {
            cp_wait<0>();
        }
        __syncthreads();

        const float* Wb = Ws + (c & 1) * 4096;
        #pragma unroll 8
        for (int kk = 0; kk < KC; ++kk) {
            const ulonglong2 fa01 = *(const ulonglong2*)&FsD[kk * 132 + 8 * ti];
            const ulonglong2 fa23 = *(const ulonglong2*)&FsD[kk * 132 + 8 * ti + 4];
            const ulonglong2 wb   = *(const ulonglong2*)&Wb[kk * 64 + 4 * tj];
            acc[0][0] = ffma2(fa01.x, wb.x, acc[0][0]); acc[0][1] = ffma2(fa01.x, wb.y, acc[0][1]);
            acc[1][0] = ffma2(fa01.y, wb.x, acc[1][0]); acc[1][1] = ffma2(fa01.y, wb.y, acc[1][1]);
            acc[2][0] = ffma2(fa23.x, wb.x, acc[2][0]); acc[2][1] = ffma2(fa23.x, wb.y, acc[2][1]);
            acc[3][0] = ffma2(fa23.y, wb.x, acc[3][0]); acc[3][1] = ffma2(fa23.y, wb.y, acc[3][1]);
        }
        __syncthreads();
    }

    // epilogue out0: columns 0..63
    #pragma unroll
    for (int r = 0; r < 4; ++r) {
        int gn = nbase + 4 * ti + r;
        if (gn < nNodes) {
            float2 lo = unpack2(acc[r][0]);
            float2 hi = unpack2(acc[r][1]);
            *(float4*)&out[(size_t)gn * DIM + 4 * tj] = make_float4(lo.x, lo.y, hi.x, hi.y);
        }
    }

    // ---------------- phase 2: out1[n,w,i] = sum_u x1[n,u,i] * (sum_v x0[n,v] W3p[u,v,w]) ----
    const int n2 = t >> 2;   // node 0..63
    const int qq = t & 3;    // w group: w = 8*qq .. 8*qq+7
    float o[24];
    #pragma unroll
    for (int j = 0; j < 24; ++j) o[j] = 0.f;

    // prefetch W3 chunk 0 (u = 0,1) — buffers free after phase-1 final sync
    {
        uint32_t dst = ws_s;
        #pragma unroll
        for (int j = 0; j < 4; ++j) {
            int e = t + THREADS * j;
            int v = e >> 4, up = (e >> 3) & 1, wq = e & 7;
            const char* g = (const char*)(g_W3p + ((0 + up) * 64 + v) * 32) + wq * 16;
            cp_async16(dst + e * 16, g);
        }
        cp_commit();
    }

    for (int uc = 0; uc < 16; ++uc) {
        if (uc + 1 < 16) {
            int u0n = 2 * (uc + 1);
            uint32_t dst = ws_s + ((uc + 1) & 1) * 16384;
            #pragma unroll
            for (int j = 0; j < 4; ++j) {
                int e = t + THREADS * j;
                int v = e >> 4, up = (e >> 3) & 1, wq = e & 7;
                const char* g = (const char*)(g_W3p + ((u0n + up) * 64 + v) * 32) + wq * 16;
                cp_async16(dst + e * 16, g);
            }
            cp_commit();
            cp_wait<1>();
        } else {
            cp_wait<0>();
        }
        __syncthreads();

        const float* W3b = Ws + (uc & 1) * 4096;   // [v][u'][w] : (v*2+u')*32 + w
        unsigned long long tacc[2][4];
        #pragma unroll
        for (int up = 0; up < 2; ++up)
            #pragma unroll
            for (int p = 0; p < 4; ++p) tacc[up][p] = 0ull;

        #pragma unroll 4
        for (int v = 0; v < 64; ++v) {
            float xv = xs0[v * TN + n2];
            unsigned long long xp = pack2(xv, xv);
            const ulonglong2 b0 = *(const ulonglong2*)&W3b[(v * 2 + 0) * 32 + 8 * qq];
            const ulonglong2 b1 = *(const ulonglong2*)&W3b[(v * 2 + 0) * 32 + 8 * qq + 4];
            const ulonglong2 b2 = *(const ulonglong2*)&W3b[(v * 2 + 1) * 32 + 8 * qq];
            const ulonglong2 b3 = *(const ulonglong2*)&W3b[(v * 2 + 1) * 32 + 8 * qq + 4];
            tacc[0][0] = ffma2(xp, b0.x, tacc[0][0]); tacc[0][1] = ffma2(xp, b0.y, tacc[0][1]);
            tacc[0][2] = ffma2(xp, b1.x, tacc[0][2]); tacc[0][3] = ffma2(xp, b1.y, tacc[0][3]);
            tacc[1][0] = ffma2(xp, b2.x, tacc[1][0]); tacc[1][1] = ffma2(xp, b2.y, tacc[1][1]);
            tacc[1][2] = ffma2(xp, b3.x, tacc[1][2]); tacc[1][3] = ffma2(xp, b3.y, tacc[1][3]);
        }

        int u0 = 2 * uc;
        #pragma unroll
        for (int up = 0; up < 2; ++up) {
            float tw[8];
            #pragma unroll
            for (int p = 0; p < 4; ++p) {
                float2 f = unpack2(tacc[up][p]);
                tw[2 * p] = f.x; tw[2 * p + 1] = f.y;
            }
            #pragma unroll
            for (int i = 0; i < 3; ++i) {
                float xi = xs1[(i * MUL1 + (u0 + up)) * TN + n2];
                #pragma unroll
                for (int w = 0; w < 8; ++w) o[3 * w + i] += xi * tw[w];
            }
        }
        __syncthreads();
    }

    // epilogue out1: thread owns 24 contiguous floats at [64 + 24*qq, 64 + 24*qq + 24)
    {
        int gn = nbase + n2;
        if (gn < nNodes) {
            float* dst = &out[(size_t)gn * DIM + MUL0 + 24 * qq];
            #pragma unroll
            for (int j = 0; j < 6; ++j)
                *(float4*)&dst[4 * j] = make_float4(o[4 * j], o[4 * j + 1], o[4 * j + 2], o[4 * j + 3]);
        }
    }
}

// ---------------- launch ----------------
extern "C" void kernel_launch(void* const* d_in, const int* in_sizes, int n_in,
                              void* d_out, int out_size) {
    const float* A  = (const float*)d_in[0];
    const float* B  = (const float*)d_in[1];
    const float* W1 = (const float*)d_in[2];
    const float* W2 = (const float*)d_in[3];
    const float* W3 = (const float*)d_in[4];
    const float* W4 = (const float*)d_in[5];
    const float* W5 = (const float*)d_in[6];
    float* out = (float*)d_out;
    int nNodes = in_sizes[0] / DIM;

    cudaFuncSetAttribute(node_block_kernel,
                         cudaFuncAttributeMaxDynamicSharedMemorySize, SMEM_BYTES);

    prep_kernel<<<256, 256>>>(W1, W2, W3, W4, W5);
    int nb = (nNodes + TN - 1) / TN;
    node_block_kernel<<<nb, THREADS, SMEM_BYTES>>>(A, B, out, nNodes);
}

// round 2
// speedup vs baseline: 1.2104x; 1.2104x over previous
#include <cuda_runtime.h>
#include <cstdint>

#define MUL0   64
#define MUL1   32
#define DIM    160
#define NPAIR0 2016
#define KTOT   2608
#define KPAD   2624
#define NCH    41           // 64-wide K chunks
#define TN     128          // nodes per block
#define THREADS 256

// ---------------- device scratch ----------------
__device__ float    g_Wc[KPAD * 64];        // combined out0 weights, scaled, padded
__device__ float    g_W3p[32 * 64 * 32];    // W3 * C1 * inv_sqrt3
__device__ unsigned g_kmap[KPAD];           // k -> u | v<<8 | type<<16

// ---------------- PTX helpers ----------------
__device__ __forceinline__ void cp_async16(uint32_t saddr, const void* gptr) {
    asm volatile("cp.async.cg.shared.global [%0], [%1], 16;\n" :: "r"(saddr), "l"(gptr));
}
__device__ __forceinline__ void cp_commit() { asm volatile("cp.async.commit_group;\n" ::: "memory"); }
template<int N> __device__ __forceinline__ void cp_wait() {
    asm volatile("cp.async.wait_group %0;\n" :: "n"(N) : "memory");
}
__device__ __forceinline__ unsigned long long ffma2(unsigned long long a, unsigned long long b,
                                                    unsigned long long c) {
    unsigned long long d;
    asm("fma.rn.f32x2 %0, %1, %2, %3;" : "=l"(d) : "l"(a), "l"(b), "l"(c));
    return d;
}
__device__ __forceinline__ unsigned long long pack2(float x, float y) {
    unsigned long long d;
    asm("mov.b64 %0, {%1, %2};" : "=l"(d) : "f"(x), "f"(y));
    return d;
}
__device__ __forceinline__ float2 unpack2(unsigned long long a) {
    float2 r; asm("mov.b64 {%0, %1}, %2;" : "=f"(r.x), "=f"(r.y) : "l"(a)); return r;
}
__device__ __forceinline__ void bar_group(int g) {
    asm volatile("bar.sync %0, 128;" :: "r"(g + 1) : "memory");
}

// ---------------- prep: pack weights + pair table ----------------
__global__ void prep_kernel(const float* __restrict__ W1, const float* __restrict__ W2,
                            const float* __restrict__ W3, const float* __restrict__ W4,
                            const float* __restrict__ W5) {
    const float C0   = sqrtf(1.0f / 2608.0f);
    const float INV3 = 0.5773502691896258f;
    const float C0I  = C0 * INV3;
    const float C1I  = sqrtf(1.0f / 2048.0f);   // C1 * inv_sqrt3

    int t = blockIdx.x * blockDim.x + threadIdx.x;
    int stride = gridDim.x * blockDim.x;

    if (t < 64 * 64) {
        int u = t >> 6, v = t & 63;
        if (u < v)  g_kmap[u * 63 - (u * (u - 1)) / 2 + (v - u - 1)] = (unsigned)(u | (v << 8));
        if (u == v) g_kmap[NPAIR0 + u] = (unsigned)(u | (u << 8));
        if (u < 32 && v < 32) {
            if (u < v)  g_kmap[2080 + u * 31 - (u * (u - 1)) / 2 + (v - u - 1)] =
                            (unsigned)(u | (v << 8) | 0x10000);
            if (u == v) g_kmap[2576 + u] = (unsigned)(u | (u << 8) | 0x10000);
        }
    }
    if (t < KPAD - KTOT) g_kmap[KTOT + t] = 0u;

    for (int idx = t; idx < KPAD * 64; idx += stride) {
        int k = idx >> 6, w = idx & 63;
        float val = 0.f;
        if (k < NPAIR0)      val = C0  * W1[idx];
        else if (k < 2080)   val = C0  * W2[(k - 2016) * 64 + w];
        else if (k < 2576)   val = C0I * W4[(k - 2080) * 64 + w];
        else if (k < KTOT)   val = C0I * W5[(k - 2576) * 64 + w];
        g_Wc[idx] = val;
    }
    for (int idx = t; idx < 32 * 64 * 32; idx += stride)
        g_W3p[idx] = C1I * W3[idx];
}

// ---------------- smem layout (floats) ----------------
#define WS_OFF   0                 // W buffers: 2 groups x 64x64 = 8192 floats (32KB)
#define FS_OFF   8192              // F buffers: 2 groups x 64x128 = 16384 floats (64KB)
#define XS0_OFF  24576             // xs0 [64][128] = 8192 floats (32KB)
#define XS1_OFF  32768             // xs1 [3][32][128] = 12288 floats (48KB)
#define SMEM_FLOATS 45056
#define SMEM_BYTES  (SMEM_FLOATS * 4)   // 180224 B

__global__ void __launch_bounds__(THREADS, 1)
node_block_kernel(const float* __restrict__ A, const float* __restrict__ B,
                  float* __restrict__ out, int nNodes) {
    extern __shared__ float sm[];
    float* Ws  = sm + WS_OFF;
    float* Fs  = sm + FS_OFF;
    float* xs0 = sm + XS0_OFF;
    float* xs1 = sm + XS1_OFF;

    const int t  = threadIdx.x;
    const int g  = t >> 7;          // split-K group 0/1
    const int tg = t & 127;
    const int nbase = blockIdx.x * TN;
    const uint32_t ws_s = (uint32_t)__cvta_generic_to_shared(Ws);

    // prologue: each group prefetches its first weight chunk (chunk index = g)
    {
        const char* gsrc = (const char*)(g_Wc + g * 4096);
        uint32_t dst = ws_s + g * 16384;
        #pragma unroll
        for (int j = 0; j < 8; ++j) { int e = tg + 128 * j; cp_async16(dst + e * 16, gsrc + e * 16); }
        cp_commit();
    }

    // load x = A + B, scatter transposed into smem (node index fastest)
    for (int e = t; e < TN * DIM; e += THREADS) {
        int n = e / DIM, d = e - n * DIM;
        int gn = nbase + n;
        float v = 0.f;
        if (gn < nNodes) v = A[(size_t)gn * DIM + d] + B[(size_t)gn * DIM + d];
        if (d < MUL0) xs0[d * TN + n] = v;
        else { int dd = d - MUL0; int u = dd / 3, i = dd - 3 * u; xs1[(i * MUL1 + u) * TN + n] = v; }
    }
    __syncthreads();

    // ---------------- phase 1: out0 = F(x) @ Wc, 2-way split-K ----------------
    const int rg  = tg >> 3;   // node octet: rows 8*rg .. 8*rg+7
    const int cg  = tg & 7;    // col octet:  cols 8*cg .. 8*cg+7
    const int nq  = tg & 31;   // gen: node quad 4*nq..
    const int kkb = tg >> 5;   // gen: kk block (uniform per warp)
    float* FsG = Fs + g * (64 * TN);
    float* Wg  = Ws + g * 4096;

    unsigned long long acc[8][4];
    #pragma unroll
    for (int r = 0; r < 8; ++r)
        #pragma unroll
        for (int p = 0; p < 4; ++p) acc[r][p] = 0ull;

    for (int ci = g; ci < NCH; ci += 2) {
        // ---- generate features for this chunk (float4 over nodes) ----
        const int kb = ci * 64;
        #pragma unroll 4
        for (int j = 0; j < 16; ++j) {
            int kk = kkb * 16 + j;
            unsigned km = g_kmap[kb + kk];
            int u = km & 255, v = (km >> 8) & 255;
            float4 val;
            if (km & 0x10000u) {
                const float4 a0 = *(const float4*)&xs1[(0 * MUL1 + u) * TN + 4 * nq];
                const float4 b0 = *(const float4*)&xs1[(0 * MUL1 + v) * TN + 4 * nq];
                const float4 a1 = *(const float4*)&xs1[(1 * MUL1 + u) * TN + 4 * nq];
                const float4 b1 = *(const float4*)&xs1[(1 * MUL1 + v) * TN + 4 * nq];
                const float4 a2 = *(const float4*)&xs1[(2 * MUL1 + u) * TN + 4 * nq];
                const float4 b2 = *(const float4*)&xs1[(2 * MUL1 + v) * TN + 4 * nq];
                val.x = a0.x * b0.x + a1.x * b1.x + a2.x * b2.x;
                val.y = a0.y * b0.y + a1.y * b1.y + a2.y * b2.y;
                val.z = a0.z * b0.z + a1.z * b1.z + a2.z * b2.z;
                val.w = a0.w * b0.w + a1.w * b1.w + a2.w * b2.w;
            } else {
                const float4 a = *(const float4*)&xs0[u * TN + 4 * nq];
                const float4 b = *(const float4*)&xs0[v * TN + 4 * nq];
                val.x = a.x * b.x; val.y = a.y * b.y; val.z = a.z * b.z; val.w = a.w * b.w;
            }
            *(float4*)&FsG[kk * TN + 4 * nq] = val;
        }
        cp_wait<0>();
        bar_group(g);   // features visible + weight chunk loaded

        // ---- GEMM: 8x8 per thread, f32x2 over col pairs ----
        #pragma unroll 2
        for (int kk = 0; kk < 64; ++kk) {
            const float4 fA = *(const float4*)&FsG[kk * TN + 8 * rg];
            const float4 fB = *(const float4*)&FsG[kk * TN + 8 * rg + 4];
            const ulonglong2 wA = *(const ulonglong2*)&Wg[kk * 64 + 8 * cg];
            const ulonglong2 wB = *(const ulonglong2*)&Wg[kk * 64 + 8 * cg + 4];
            float fr[8] = {fA.x, fA.y, fA.z, fA.w, fB.x, fB.y, fB.z, fB.w};
            #pragma unroll
            for (int r = 0; r < 8; ++r) {
                unsigned long long fd = pack2(fr[r], fr[r]);
                acc[r][0] = ffma2(fd, wA.x, acc[r][0]);
                acc[r][1] = ffma2(fd, wA.y, acc[r][1]);
                acc[r][2] = ffma2(fd, wB.x, acc[r][2]);
                acc[r][3] = ffma2(fd, wB.y, acc[r][3]);
            }
        }
        bar_group(g);   // group done reading Fs/W -> safe to overwrite

        if (ci + 2 < NCH) {
            const char* gsrc = (const char*)(g_Wc + (ci + 2) * 4096);
            uint32_t dst = ws_s + g * 16384;
            #pragma unroll
            for (int j = 0; j < 8; ++j) { int e = tg + 128 * j; cp_async16(dst + e * 16, gsrc + e * 16); }
            cp_commit();
        }
    }

    // ---- reduce the two K-partials, store out0 ----
    float* SAcc = Fs;   // 8192 floats, group-0 Fs region (free by now)
    if (g == 0) {
        #pragma unroll
        for (int r = 0; r < 8; ++r)
            #pragma unroll
            for (int p = 0; p < 4; ++p)
                *(float2*)&SAcc[(8 * rg + r) * 64 + 8 * cg + 2 * p] = unpack2(acc[r][p]);
    }
    __syncthreads();
    if (g == 1) {
        #pragma unroll
        for (int r = 0; r < 8; ++r) {
            int gn = nbase + 8 * rg + r;
            if (gn < nNodes) {
                float o8[8];
                #pragma unroll
                for (int p = 0; p < 4; ++p) {
                    float2 s = *(float2*)&SAcc[(8 * rg + r) * 64 + 8 * cg + 2 * p];
                    float2 m = unpack2(acc[r][p]);
                    o8[2 * p] = s.x + m.x; o8[2 * p + 1] = s.y + m.y;
                }
                float* dst = &out[(size_t)gn * DIM + 8 * cg];
                *(float4*)&dst[0] = make_float4(o8[0], o8[1], o8[2], o8[3]);
                *(float4*)&dst[4] = make_float4(o8[4], o8[5], o8[6], o8[7]);
            }
        }
    }
    __syncthreads();

    // ---------------- phase 2: out1, two passes of 64 nodes ----------------
    for (int pass = 0; pass < 2; ++pass) {
        const int n2 = pass * 64 + (t >> 2);
        const int qq = t & 3;
        float o[24];
        #pragma unroll
        for (int j = 0; j < 24; ++j) o[j] = 0.f;

        // prefetch W3 chunk 0 (u = 0,1)
        {
            uint32_t dst = ws_s;
            #pragma unroll
            for (int j = 0; j < 4; ++j) {
                int e = t + THREADS * j;
                int v = e >> 4, up = (e >> 3) & 1, wq = e & 7;
                const char* gp = (const char*)(g_W3p + ((0 + up) * 64 + v) * 32) + wq * 16;
                cp_async16(dst + e * 16, gp);
            }
            cp_commit();
        }

        for (int uc = 0; uc < 16; ++uc) {
            if (uc + 1 < 16) {
                int u0n = 2 * (uc + 1);
                uint32_t dst = ws_s + ((uc + 1) & 1) * 16384;
                #pragma unroll
                for (int j = 0; j < 4; ++j) {
                    int e = t + THREADS * j;
                    int v = e >> 4, up = (e >> 3) & 1, wq = e & 7;
                    const char* gp = (const char*)(g_W3p + ((u0n + up) * 64 + v) * 32) + wq * 16;
                    cp_async16(dst + e * 16, gp);
                }
                cp_commit();
                cp_wait<1>();
            } else {
                cp_wait<0>();
            }
            __syncthreads();

            const float* W3b = Ws + (uc & 1) * 4096;   // [v][u'][w]
            unsigned long long tacc[2][4];
            #pragma unroll
            for (int up = 0; up < 2; ++up)
                #pragma unroll
                for (int p = 0; p < 4; ++p) tacc[up][p] = 0ull;

            #pragma unroll 4
            for (int v = 0; v < 64; ++v) {
                float xv = xs0[v * TN + n2];
                unsigned long long xp = pack2(xv, xv);
                const ulonglong2 b0 = *(const ulonglong2*)&W3b[(v * 2 + 0) * 32 + 8 * qq];
                const ulonglong2 b1 = *(const ulonglong2*)&W3b[(v * 2 + 0) * 32 + 8 * qq + 4];
                const ulonglong2 b2 = *(const ulonglong2*)&W3b[(v * 2 + 1) * 32 + 8 * qq];
                const ulonglong2 b3 = *(const ulonglong2*)&W3b[(v * 2 + 1) * 32 + 8 * qq + 4];
                tacc[0][0] = ffma2(xp, b0.x, tacc[0][0]); tacc[0][1] = ffma2(xp, b0.y, tacc[0][1]);
                tacc[0][2] = ffma2(xp, b1.x, tacc[0][2]); tacc[0][3] = ffma2(xp, b1.y, tacc[0][3]);
                tacc[1][0] = ffma2(xp, b2.x, tacc[1][0]); tacc[1][1] = ffma2(xp, b2.y, tacc[1][1]);
                tacc[1][2] = ffma2(xp, b3.x, tacc[1][2]); tacc[1][3] = ffma2(xp, b3.y, tacc[1][3]);
            }

            int u0 = 2 * uc;
            #pragma unroll
            for (int up = 0; up < 2; ++up) {
                float tw[8];
                #pragma unroll
                for (int p = 0; p < 4; ++p) {
                    float2 f = unpack2(tacc[up][p]);
                    tw[2 * p] = f.x; tw[2 * p + 1] = f.y;
                }
                #pragma unroll
                for (int i = 0; i < 3; ++i) {
                    float xi = xs1[(i * MUL1 + (u0 + up)) * TN + n2];
                    #pragma unroll
                    for (int w = 0; w < 8; ++w) o[3 * w + i] += xi * tw[w];
                }
            }
            __syncthreads();
        }

        // store out1 for this pass
        {
            int gn = nbase + n2;
            if (gn < nNodes) {
                float* dst = &out[(size_t)gn * DIM + MUL0 + 24 * qq];
                #pragma unroll
                for (int j = 0; j < 6; ++j)
                    *(float4*)&dst[4 * j] =
                        make_float4(o[4 * j], o[4 * j + 1], o[4 * j + 2], o[4 * j + 3]);
            }
        }
    }
}

// ---------------- launch ----------------
extern "C" void kernel_launch(void* const* d_in, const int* in_sizes, int n_in,
                              void* d_out, int out_size) {
    const float* A  = (const float*)d_in[0];
    const float* B  = (const float*)d_in[1];
    const float* W1 = (const float*)d_in[2];
    const float* W2 = (const float*)d_in[3];
    const float* W3 = (const float*)d_in[4];
    const float* W4 = (const float*)d_in[5];
    const float* W5 = (const float*)d_in[6];
    float* out = (float*)d_out;
    int nNodes = in_sizes[0] / DIM;

    cudaFuncSetAttribute(node_block_kernel,
                         cudaFuncAttributeMaxDynamicSharedMemorySize, SMEM_BYTES);

    prep_kernel<<<256, 256>>>(W1, W2, W3, W4, W5);
    int nb = (nNodes + TN - 1) / TN;
    node_block_kernel<<<nb, THREADS, SMEM_BYTES>>>(A, B, out, nNodes);
}

// round 4
// speedup vs baseline: 2.9634x; 2.4483x over previous
#include <cuda_runtime.h>
#include <cstdint>

#define MUL0   64
#define MUL1   32
#define DIM    160
#define NPAIR0 2016
#define KTOT   2608
#define KPAD   2624
#define NCH    41          // 64-wide K chunks, phase 1
#define NCH2   16          // 64-wide N chunks, phase 2
#define TN     128
#define THREADS 256

#define FSTR   72          // F row stride (8 mod 32 -> conflict-free frags)
#define WSTR   72          // weight tile row stride
#define XSTR   132         // xs0l/xs1l row stride (node-major)

// ---------------- device scratch ----------------
__device__ float    g_WcB[NCH * 64 * WSTR];    // phase-1 B tiles [c][k][n], tf32, scaled
__device__ float    g_W3B[NCH2 * 64 * WSTR];   // phase-2 B tiles [ci][v][col], tf32, scaled
__device__ unsigned g_kmap[KPAD];              // k -> u | v<<8 | type<<16

// ---------------- helpers ----------------
__device__ __forceinline__ float to_tf32(float x) {
    uint32_t r; asm("cvt.rna.tf32.f32 %0, %1;" : "=r"(r) : "f"(x));
    return __uint_as_float(r);
}
__device__ __forceinline__ void cp_async16(uint32_t saddr, const void* gptr) {
    asm volatile("cp.async.cg.shared.global [%0], [%1], 16;\n" :: "r"(saddr), "l"(gptr));
}
__device__ __forceinline__ void cp_commit() { asm volatile("cp.async.commit_group;\n" ::: "memory"); }
__device__ __forceinline__ void cp_wait0() { asm volatile("cp.async.wait_group 0;\n" ::: "memory"); }

__device__ __forceinline__ void mma_tf32(float* d, const uint32_t* a, const uint32_t* b) {
    asm volatile("mma.sync.aligned.m16n8k8.row.col.f32.tf32.tf32.f32 "
        "{%0,%1,%2,%3}, {%4,%5,%6,%7}, {%8,%9}, {%0,%1,%2,%3};"
        : "+f"(d[0]), "+f"(d[1]), "+f"(d[2]), "+f"(d[3])
        : "r"(a[0]), "r"(a[1]), "r"(a[2]), "r"(a[3]), "r"(b[0]), "r"(b[1]));
}
__device__ __forceinline__ uint32_t fbits(float x) { return __float_as_uint(x); }

// ---------------- prep: pack weights (tf32, scaled, strided) + pair table ----------------
__global__ void prep_kernel(const float* __restrict__ W1, const float* __restrict__ W2,
                            const float* __restrict__ W3, const float* __restrict__ W4,
                            const float* __restrict__ W5) {
    const float C0   = sqrtf(1.0f / 2608.0f);
    const float INV3 = 0.5773502691896258f;
    const float C0I  = C0 * INV3;
    const float C1I  = sqrtf(1.0f / 2048.0f);   // C1 * inv_sqrt3

    int t = blockIdx.x * blockDim.x + threadIdx.x;
    int stride = gridDim.x * blockDim.x;

    if (t < 64 * 64) {
        int u = t >> 6, v = t & 63;
        if (u < v)  g_kmap[u * 63 - (u * (u - 1)) / 2 + (v - u - 1)] = (unsigned)(u | (v << 8));
        if (u == v) g_kmap[NPAIR0 + u] = (unsigned)(u | (u << 8));
        if (u < 32 && v < 32) {
            if (u < v)  g_kmap[2080 + u * 31 - (u * (u - 1)) / 2 + (v - u - 1)] =
                            (unsigned)(u | (v << 8) | 0x10000);
            if (u == v) g_kmap[2576 + u] = (unsigned)(u | (u << 8) | 0x10000);
        }
    }
    if (t < KPAD - KTOT) g_kmap[KTOT + t] = 0u;

    // phase-1 B tiles: [c][k_local][n], n stride WSTR
    for (int idx = t; idx < NCH * 64 * WSTR; idx += stride) {
        int c = idx / (64 * WSTR);
        int rem = idx - c * 64 * WSTR;
        int kl = rem / WSTR, n = rem - kl * WSTR;
        float val = 0.f;
        if (n < 64) {
            int k = c * 64 + kl;
            if (k < NPAIR0)      val = C0  * W1[k * 64 + n];
            else if (k < 2080)   val = C0  * W2[(k - 2016) * 64 + n];
            else if (k < 2576)   val = C0I * W4[(k - 2080) * 64 + n];
            else if (k < KTOT)   val = C0I * W5[(k - 2576) * 64 + n];
            val = to_tf32(val);
        }
        g_WcB[idx] = val;
    }
    // phase-2 B tiles: [ci][v][col], col = ul*32 + w (ul in 0..1 -> u = 2ci+ul)
    for (int idx = t; idx < NCH2 * 64 * WSTR; idx += stride) {
        int ci = idx / (64 * WSTR);
        int rem = idx - ci * 64 * WSTR;
        int v = rem / WSTR, col = rem - v * WSTR;
        float val = 0.f;
        if (col < 64) {
            int u = 2 * ci + (col >> 5), w = col & 31;
            val = to_tf32(C1I * W3[(u * 64 + v) * 32 + w]);
        }
        g_W3B[idx] = val;
    }
}

// ---------------- smem layout (float indices) ----------------
#define XS0L_OFF 0                         // xs0l [64][132]  = 8448
#define XS1L_OFF 8448                      // xs1l [96][132]  = 12672
#define X0R_OFF  21120                     // x0r  [128][72]  = 9216 (tf32)
#define F_OFF    30336                     // F/Y double buffer: 2 x 128x72 = 18432
#define W_OFF    48768                     // W double buffer: 2 x 64x72 = 9216
#define SMEM_FLOATS 57984
#define SMEM_BYTES  (SMEM_FLOATS * 4)      // 231936 B

#define WCHUNK_FLOATS (64 * WSTR)          // 4608
#define FBUF_FLOATS   (128 * FSTR)         // 9216

__global__ void __launch_bounds__(THREADS)
node_block_kernel(const float* __restrict__ A, const float* __restrict__ B,
                  float* __restrict__ out, int nNodes) {
    extern __shared__ float sm[];
    float* xs0l = sm + XS0L_OFF;
    float* xs1l = sm + XS1L_OFF;
    float* x0r  = sm + X0R_OFF;
    float* Fbuf = sm + F_OFF;
    float* Wbuf = sm + W_OFF;

    const int t    = threadIdx.x;
    const int lane = t & 31;
    const int warp = t >> 5;
    const int rg   = warp >> 1;      // row group (32 rows)
    const int cg   = warp & 1;       // col group (32 cols)
    const int gy   = lane >> 2;      // frag row-in-tile / B col
    const int gx   = lane & 3;       // frag col / B row
    const int nbase = blockIdx.x * TN;
    const uint32_t w_s = (uint32_t)__cvta_generic_to_shared(Wbuf);

    // prefetch Wc chunk 0 into W[0]
    {
        const char* src = (const char*)&g_WcB[0];
        #pragma unroll
        for (int j = 0; j < 5; ++j) {
            int e = t + THREADS * j;
            if (e < WCHUNK_FLOATS / 4) cp_async16(w_s + e * 16, src + e * 16);
        }
        cp_commit();
    }

    // load x = A + B into xs0l, xs1l (fp32) and x0r (tf32, row-major)
    for (int e = t; e < TN * DIM; e += THREADS) {
        int n = e / DIM, d = e - n * DIM;
        int gn = nbase + n;
        float v = 0.f;
        if (gn < nNodes) v = A[(size_t)gn * DIM + d] + B[(size_t)gn * DIM + d];
        if (d < MUL0) {
            xs0l[d * XSTR + n] = v;
            x0r[n * FSTR + d] = to_tf32(v);
        } else {
            int dd = d - MUL0; int u = dd / 3, i = dd - 3 * u;
            xs1l[(i * MUL1 + u) * XSTR + n] = v;
        }
    }
    __syncthreads();

    // ================= phase 1: out0 = F(x) @ WcT =================
    float d1[2][4][4];
    #pragma unroll
    for (int mt = 0; mt < 2; ++mt)
        #pragma unroll
        for (int nt = 0; nt < 4; ++nt)
            #pragma unroll
            for (int p = 0; p < 4; ++p) d1[mt][nt][p] = 0.f;

    for (int c = 0; c < NCH; ++c) {
        const int b = c & 1;
        float* Fb = Fbuf + b * FBUF_FLOATS;
        const float* Wb = Wbuf + b * WCHUNK_FLOATS;

        // ---- generate feature chunk c into F[b] (tf32-rounded) ----
        {
            const unsigned* kmp = &g_kmap[c * 64];
            #pragma unroll
            for (int j = 0; j < 8; ++j) {
                int k  = (lane & 31) + 32 * (j & 1);
                int ng = warp * 4 + (j >> 1);
                int n4 = 4 * ng;
                unsigned km = kmp[k];
                int u = km & 255, v = (km >> 8) & 255;
                float4 val;
                if (km & 0x10000u) {
                    const float4 a0 = *(const float4*)&xs1l[(0 * MUL1 + u) * XSTR + n4];
                    const float4 b0 = *(const float4*)&xs1l[(0 * MUL1 + v) * XSTR + n4];
                    const float4 a1 = *(const float4*)&xs1l[(1 * MUL1 + u) * XSTR + n4];
                    const float4 b1 = *(const float4*)&xs1l[(1 * MUL1 + v) * XSTR + n4];
                    const float4 a2 = *(const float4*)&xs1l[(2 * MUL1 + u) * XSTR + n4];
                    const float4 b2 = *(const float4*)&xs1l[(2 * MUL1 + v) * XSTR + n4];
                    val.x = a0.x * b0.x + a1.x * b1.x + a2.x * b2.x;
                    val.y = a0.y * b0.y + a1.y * b1.y + a2.y * b2.y;
                    val.z = a0.z * b0.z + a1.z * b1.z + a2.z * b2.z;
                    val.w = a0.w * b0.w + a1.w * b1.w + a2.w * b2.w;
                } else {
                    const float4 a = *(const float4*)&xs0l[u * XSTR + n4];
                    const float4 bb = *(const float4*)&xs0l[v * XSTR + n4];
                    val.x = a.x * bb.x; val.y = a.y * bb.y;
                    val.z = a.z * bb.z; val.w = a.w * bb.w;
                }
                Fb[(n4 + 0) * FSTR + k] = to_tf32(val.x);
                Fb[(n4 + 1) * FSTR + k] = to_tf32(val.y);
                Fb[(n4 + 2) * FSTR + k] = to_tf32(val.z);
                Fb[(n4 + 3) * FSTR + k] = to_tf32(val.w);
            }
        }
        cp_wait0();
        __syncthreads();

        // prefetch next weight chunk
        if (c + 1 < NCH) {
            const char* src = (const char*)&g_WcB[(c + 1) * WCHUNK_FLOATS];
            uint32_t dst = w_s + ((c + 1) & 1) * WCHUNK_FLOATS * 4;
            #pragma unroll
            for (int j = 0; j < 5; ++j) {
                int e = t + THREADS * j;
                if (e < WCHUNK_FLOATS / 4) cp_async16(dst + e * 16, src + e * 16);
            }
            cp_commit();
        }

        // ---- warp-tiled mma: 32x32 per warp, K=64 ----
        #pragma unroll 2
        for (int ks = 0; ks < 8; ++ks) {
            const int k0 = 8 * ks;
            uint32_t a[2][4], bf[4][2];
            #pragma unroll
            for (int mt = 0; mt < 2; ++mt) {
                int base = (32 * rg + 16 * mt + gy) * FSTR + k0 + gx;
                a[mt][0] = fbits(Fb[base]);
                a[mt][1] = fbits(Fb[base + 8 * FSTR]);
                a[mt][2] = fbits(Fb[base + 4]);
                a[mt][3] = fbits(Fb[base + 8 * FSTR + 4]);
            }
            #pragma unroll
            for (int nt = 0; nt < 4; ++nt) {
                int bbase = (k0 + gx) * WSTR + 32 * cg + 8 * nt + gy;
                bf[nt][0] = fbits(Wb[bbase]);
                bf[nt][1] = fbits(Wb[bbase + 4 * WSTR]);
            }
            #pragma unroll
            for (int mt = 0; mt < 2; ++mt)
                #pragma unroll
                for (int nt = 0; nt < 4; ++nt)
                    mma_tf32(d1[mt][nt], a[mt], bf[nt]);
        }
    }
    __syncthreads();   // phase-1 smem reads done; F/W areas reusable

    // prefetch W3 chunk 0 into W[0]
    {
        const char* src = (const char*)&g_W3B[0];
        #pragma unroll
        for (int j = 0; j < 5; ++j) {
            int e = t + THREADS * j;
            if (e < WCHUNK_FLOATS / 4) cp_async16(w_s + e * 16, src + e * 16);
        }
        cp_commit();
    }

    // ---- phase-1 epilogue: store out0 fragments ----
    #pragma unroll
    for (int mt = 0; mt < 2; ++mt) {
        #pragma unroll
        for (int nt = 0; nt < 4; ++nt) {
            int r = 32 * rg + 16 * mt + gy;
            int cc = 32 * cg + 8 * nt + 2 * gx;
            int gn = nbase + r;
            if (gn < nNodes)
                *(float2*)&out[(size_t)gn * DIM + cc] = make_float2(d1[mt][nt][0], d1[mt][nt][1]);
            int gn2 = nbase + r + 8;
            if (gn2 < nNodes)
                *(float2*)&out[(size_t)gn2 * DIM + cc] = make_float2(d1[mt][nt][2], d1[mt][nt][3]);
        }
    }

    // ================= phase 2: Y = x0 @ W3r (16 chunks of 64 cols) =================
    const int n2 = t >> 1;    // node 0..127
    const int h  = t & 1;     // w half: w in [16h, 16h+16)
    float o[48];
    #pragma unroll
    for (int j = 0; j < 48; ++j) o[j] = 0.f;

    for (int ci = 0; ci < NCH2; ++ci) {
        const int b = ci & 1;
        float* Yb = Fbuf + b * FBUF_FLOATS;
        const float* Wb = Wbuf + b * WCHUNK_FLOATS;

        cp_wait0();
        __syncthreads();   // W3[ci] ready; Y[b] readers (chunk ci-2) done

        float d2[2][4][4];
        #pragma unroll
        for (int mt = 0; mt < 2; ++mt)
            #pragma unroll
            for (int nt = 0; nt < 4; ++nt)
                #pragma unroll
                for (int p = 0; p < 4; ++p) d2[mt][nt][p] = 0.f;

        #pragma unroll 2
        for (int ks = 0; ks < 8; ++ks) {
            const int k0 = 8 * ks;
            uint32_t a[2][4], bf[4][2];
            #pragma unroll
            for (int mt = 0; mt < 2; ++mt) {
                int base = (32 * rg + 16 * mt + gy) * FSTR + k0 + gx;
                a[mt][0] = fbits(x0r[base]);
                a[mt][1] = fbits(x0r[base + 8 * FSTR]);
                a[mt][2] = fbits(x0r[base + 4]);
                a[mt][3] = fbits(x0r[base + 8 * FSTR + 4]);
            }
            #pragma unroll
            for (int nt = 0; nt < 4; ++nt) {
                int bbase = (k0 + gx) * WSTR + 32 * cg + 8 * nt + gy;
                bf[nt][0] = fbits(Wb[bbase]);
                bf[nt][1] = fbits(Wb[bbase + 4 * WSTR]);
            }
            #pragma unroll
            for (int mt = 0; mt < 2; ++mt)
                #pragma unroll
                for (int nt = 0; nt < 4; ++nt)
                    mma_tf32(d2[mt][nt], a[mt], bf[nt]);
        }

        // store Y fragments to smem
        #pragma unroll
        for (int mt = 0; mt < 2; ++mt) {
            #pragma unroll
            for (int nt = 0; nt < 4; ++nt) {
                int r = 32 * rg + 16 * mt + gy;
                int cc = 32 * cg + 8 * nt + 2 * gx;
                *(float2*)&Yb[r * FSTR + cc]       = make_float2(d2[mt][nt][0], d2[mt][nt][1]);
                *(float2*)&Yb[(r + 8) * FSTR + cc] = make_float2(d2[mt][nt][2], d2[mt][nt][3]);
            }
        }
        __syncthreads();   // Y[b] visible; W3[b] free

        if (ci + 1 < NCH2) {
            const char* src = (const char*)&g_W3B[(ci + 1) * WCHUNK_FLOATS];
            uint32_t dst = w_s + ((ci + 1) & 1) * WCHUNK_FLOATS * 4;
            #pragma unroll
            for (int j = 0; j < 5; ++j) {
                int e = t + THREADS * j;
                if (e < WCHUNK_FLOATS / 4) cp_async16(dst + e * 16, src + e * 16);
            }
            cp_commit();
        }

        // contraction: o[w,i] += Y[n, ul*32+w] * x1[n, u, i]
        #pragma unroll
        for (int ul = 0; ul < 2; ++ul) {
            int u = 2 * ci + ul;
            float xi0 = xs1l[(0 * MUL1 + u) * XSTR + n2];
            float xi1 = xs1l[(1 * MUL1 + u) * XSTR + n2];
            float xi2 = xs1l[(2 * MUL1 + u) * XSTR + n2];
            #pragma unroll
            for (int q = 0; q < 4; ++q) {
                float4 y = *(const float4*)&Yb[n2 * FSTR + ul * 32 + 16 * h + 4 * q];
                float yv[4] = {y.x, y.y, y.z, y.w};
                #pragma unroll
                for (int e = 0; e < 4; ++e) {
                    int lw = 4 * q + e;
                    o[lw * 3 + 0] += yv[e] * xi0;
                    o[lw * 3 + 1] += yv[e] * xi1;
                    o[lw * 3 + 2] += yv[e] * xi2;
                }
            }
        }
    }

    // out1 store: 48 contiguous floats at 64 + 48*h
    {
        int gn = nbase + n2;
        if (gn < nNodes) {
            float* dst = &out[(size_t)gn * DIM + MUL0 + 48 * h];
            #pragma unroll
            for (int j = 0; j < 12; ++j)
                *(float4*)&dst[4 * j] = make_float4(o[4 * j], o[4 * j + 1], o[4 * j + 2], o[4 * j + 3]);
        }
    }
}

// ---------------- launch ----------------
extern "C" void kernel_launch(void* const* d_in, const int* in_sizes, int n_in,
                              void* d_out, int out_size) {
    const float* A  = (const float*)d_in[0];
    const float* B  = (const float*)d_in[1];
    const float* W1 = (const float*)d_in[2];
    const float* W2 = (const float*)d_in[3];
    const float* W3 = (const float*)d_in[4];
    const float* W4 = (const float*)d_in[5];
    const float* W5 = (const float*)d_in[6];
    float* out = (float*)d_out;
    int nNodes = in_sizes[0] / DIM;

    cudaFuncSetAttribute(node_block_kernel,
                         cudaFuncAttributeMaxDynamicSharedMemorySize, SMEM_BYTES);

    prep_kernel<<<256, 256>>>(W1, W2, W3, W4, W5);
    int nb = (nNodes + TN - 1) / TN;
    node_block_kernel<<<nb, THREADS, SMEM_BYTES>>>(A, B, out, nNodes);
}

// round 8
// speedup vs baseline: 3.9579x; 1.3356x over previous
#include <cuda_runtime.h>
#include <cstdint>

#define MUL0   64
#define MUL1   32
#define DIM    160
#define NPAIR0 2016
#define KTOT   2608
#define KPAD   2624
#define NCH    41          // 64-wide K chunks, phase 1
#define NCH2   16          // 64-wide N chunks, phase 2
#define TN     128
#define THREADS 512        // 8 producer warps + 8 consumer warps

#define FSTR   68          // F / x0r row stride (== 4 mod 32 -> conflict-free A frags)
#define WSTR   72          // weight tile row stride (== 8 mod 32 -> conflict-free B frags)
#define XSTR   132         // xs0l/xs1l row stride

// ---------------- device scratch ----------------
__device__ float    g_WcB[NCH * 64 * WSTR];    // phase-1 B tiles [c][k][n], tf32, scaled
__device__ float    g_W3B[NCH2 * 64 * WSTR];   // phase-2 B tiles [ci][v][col], tf32, scaled
__device__ unsigned g_kmap[KPAD];              // k -> u | v<<8 | type<<16

// ---------------- helpers ----------------
__device__ __forceinline__ float to_tf32(float x) {
    uint32_t r; asm("cvt.rna.tf32.f32 %0, %1;" : "=r"(r) : "f"(x));
    return __uint_as_float(r);
}
__device__ __forceinline__ void cp_async16(uint32_t saddr, const void* gptr) {
    asm volatile("cp.async.cg.shared.global [%0], [%1], 16;\n" :: "r"(saddr), "l"(gptr));
}
__device__ __forceinline__ void cp_commit() { asm volatile("cp.async.commit_group;\n" ::: "memory"); }
__device__ __forceinline__ void cp_wait0() { asm volatile("cp.async.wait_group 0;\n" ::: "memory"); }
// consumer-group barrier: makes all consumers' landed cp.async data visible to each other
__device__ __forceinline__ void bar_cons() {
    asm volatile("bar.sync 1, 256;" ::: "memory");
}

__device__ __forceinline__ void mma_tf32(float* d, const uint32_t* a, const uint32_t* b) {
    asm volatile("mma.sync.aligned.m16n8k8.row.col.f32.tf32.tf32.f32 "
        "{%0,%1,%2,%3}, {%4,%5,%6,%7}, {%8,%9}, {%0,%1,%2,%3};"
        : "+f"(d[0]), "+f"(d[1]), "+f"(d[2]), "+f"(d[3])
        : "r"(a[0]), "r"(a[1]), "r"(a[2]), "r"(a[3]), "r"(b[0]), "r"(b[1]));
}
__device__ __forceinline__ uint32_t fbits(float x) { return __float_as_uint(x); }

// ---------------- prep: pack weights (tf32, scaled, strided) + pair table ----------------
__global__ void prep_kernel(const float* __restrict__ W1, const float* __restrict__ W2,
                            const float* __restrict__ W3, const float* __restrict__ W4,
                            const float* __restrict__ W5) {
    const float C0   = sqrtf(1.0f / 2608.0f);
    const float INV3 = 0.5773502691896258f;
    const float C0I  = C0 * INV3;
    const float C1I  = sqrtf(1.0f / 2048.0f);   // C1 * inv_sqrt3

    int t = blockIdx.x * blockDim.x + threadIdx.x;
    int stride = gridDim.x * blockDim.x;

    if (t < 64 * 64) {
        int u = t >> 6, v = t & 63;
        if (u < v)  g_kmap[u * 63 - (u * (u - 1)) / 2 + (v - u - 1)] = (unsigned)(u | (v << 8));
        if (u == v) g_kmap[NPAIR0 + u] = (unsigned)(u | (u << 8));
        if (u < 32 && v < 32) {
            if (u < v)  g_kmap[2080 + u * 31 - (u * (u - 1)) / 2 + (v - u - 1)] =
                            (unsigned)(u | (v << 8) | 0x10000);
            if (u == v) g_kmap[2576 + u] = (unsigned)(u | (u << 8) | 0x10000);
        }
    }
    if (t < KPAD - KTOT) g_kmap[KTOT + t] = 0u;

    // phase-1 B tiles: [c][k_local][n], n stride WSTR
    for (int idx = t; idx < NCH * 64 * WSTR; idx += stride) {
        int c = idx / (64 * WSTR);
        int rem = idx - c * 64 * WSTR;
        int kl = rem / WSTR, n = rem - kl * WSTR;
        float val = 0.f;
        if (n < 64) {
            int k = c * 64 + kl;
            if (k < NPAIR0)      val = C0  * W1[k * 64 + n];
            else if (k < 2080)   val = C0  * W2[(k - 2016) * 64 + n];
            else if (k < 2576)   val = C0I * W4[(k - 2080) * 64 + n];
            else if (k < KTOT)   val = C0I * W5[(k - 2576) * 64 + n];
            val = to_tf32(val);
        }
        g_WcB[idx] = val;
    }
    // phase-2 B tiles: [ci][v][col], col = ul*32 + w  (u = 2*ci + ul)
    for (int idx = t; idx < NCH2 * 64 * WSTR; idx += stride) {
        int ci = idx / (64 * WSTR);
        int rem = idx - ci * 64 * WSTR;
        int v = rem / WSTR, col = rem - v * WSTR;
        float val = 0.f;
        if (col < 64) {
            int u = 2 * ci + (col >> 5), w = col & 31;
            val = to_tf32(C1I * W3[(u * 64 + v) * 32 + w]);
        }
        g_W3B[idx] = val;
    }
}

// ---------------- smem layout (float indices) ----------------
#define XS0L_OFF 0                          // xs0l [64][132]  = 8448
#define XS1L_OFF 8448                       // xs1l [96][132]  = 12672
#define X0R_OFF  21120                      // x0r  [128][68]  = 8704 (tf32)
#define F_OFF    29824                      // F/Y double buffer: 2 x 128x68 = 17408
#define W_OFF    47232                      // W double buffer: 2 x 64x72 = 9216
#define SMEM_FLOATS 56448
#define SMEM_BYTES  (SMEM_FLOATS * 4)       // 225792 B

#define WCHUNK_FLOATS (64 * WSTR)           // 4608
#define FBUF_FLOATS   (128 * FSTR)          // 8704

__global__ void __launch_bounds__(THREADS)
node_block_kernel(const float* __restrict__ A, const float* __restrict__ B,
                  float* __restrict__ out, int nNodes) {
    extern __shared__ float sm[];
    float* xs0l = sm + XS0L_OFF;
    float* xs1l = sm + XS1L_OFF;
    float* x0r  = sm + X0R_OFF;
    float* Fbuf = sm + F_OFF;
    float* Wbuf = sm + W_OFF;

    const int t    = threadIdx.x;
    const int lane = t & 31;
    const int warp = t >> 5;
    const bool prod = (warp < 8);       // producers: gen / contraction
    const int cw   = warp - 8;          // consumer warp 0..7
    const int rg   = (cw >> 1) & 3;     // row group (32 rows)
    const int cg   = cw & 1;            // col group (32 cols)
    const int gy   = lane >> 2;
    const int gx   = lane & 3;
    const int nbase = blockIdx.x * TN;
    const uint32_t w_s = (uint32_t)__cvta_generic_to_shared(Wbuf);
    const int tc = t & 255;             // index within group

    // consumers prefetch Wc chunk 0 into W[0]
    if (!prod) {
        const char* src = (const char*)&g_WcB[0];
        #pragma unroll
        for (int j = 0; j < 5; ++j) {
            int e = tc + 256 * j;
            if (e < WCHUNK_FLOATS / 4) cp_async16(w_s + e * 16, src + e * 16);
        }
        cp_commit();
    }

    // all threads: load x = A + B into xs0l, xs1l (fp32) and x0r (tf32)
    for (int e = t; e < TN * DIM; e += THREADS) {
        int n = e / DIM, d = e - n * DIM;
        int gn = nbase + n;
        float v = 0.f;
        if (gn < nNodes) v = A[(size_t)gn * DIM + d] + B[(size_t)gn * DIM + d];
        if (d < MUL0) {
            xs0l[d * XSTR + n] = v;
            x0r[n * FSTR + d] = to_tf32(v);
        } else {
            int dd = d - MUL0; int u = dd / 3, i = dd - 3 * u;
            xs1l[(i * MUL1 + u) * XSTR + n] = v;
        }
    }
    __syncthreads();

    // ================= phase 1: out0 = F(x) @ WcT (producer/consumer pipeline) ========
    float d1[2][4][4];
    if (!prod) {
        #pragma unroll
        for (int mt = 0; mt < 2; ++mt)
            #pragma unroll
            for (int nt = 0; nt < 4; ++nt)
                #pragma unroll
                for (int p = 0; p < 4; ++p) d1[mt][nt][p] = 0.f;
    }

    // producers: gen chunk 0
    if (prod) {
        const unsigned* kmp = &g_kmap[0];
        float* Fb = Fbuf;
        #pragma unroll
        for (int j = 0; j < 8; ++j) {
            int k  = lane + 32 * (j & 1);
            int n4 = 4 * (warp * 4 + (j >> 1));
            unsigned km = kmp[k];
            int u = km & 255, v = (km >> 8) & 255;
            float4 val;
            if (km & 0x10000u) {
                const float4 a0 = *(const float4*)&xs1l[(0 * MUL1 + u) * XSTR + n4];
                const float4 b0 = *(const float4*)&xs1l[(0 * MUL1 + v) * XSTR + n4];
                const float4 a1 = *(const float4*)&xs1l[(1 * MUL1 + u) * XSTR + n4];
                const float4 b1 = *(const float4*)&xs1l[(1 * MUL1 + v) * XSTR + n4];
                const float4 a2 = *(const float4*)&xs1l[(2 * MUL1 + u) * XSTR + n4];
                const float4 b2 = *(const float4*)&xs1l[(2 * MUL1 + v) * XSTR + n4];
                val.x = a0.x * b0.x + a1.x * b1.x + a2.x * b2.x;
                val.y = a0.y * b0.y + a1.y * b1.y + a2.y * b2.y;
                val.z = a0.z * b0.z + a1.z * b1.z + a2.z * b2.z;
                val.w = a0.w * b0.w + a1.w * b1.w + a2.w * b2.w;
            } else {
                const float4 a = *(const float4*)&xs0l[u * XSTR + n4];
                const float4 bb = *(const float4*)&xs0l[v * XSTR + n4];
                val.x = a.x * bb.x; val.y = a.y * bb.y;
                val.z = a.z * bb.z; val.w = a.w * bb.w;
            }
            Fb[(n4 + 0) * FSTR + k] = to_tf32(val.x);
            Fb[(n4 + 1) * FSTR + k] = to_tf32(val.y);
            Fb[(n4 + 2) * FSTR + k] = to_tf32(val.z);
            Fb[(n4 + 3) * FSTR + k] = to_tf32(val.w);
        }
    }
    __syncthreads();

    for (int c = 0; c < NCH; ++c) {
        if (prod) {
            // ---- generate chunk c+1 into F[(c+1)&1] ----
            if (c + 1 < NCH) {
                const unsigned* kmp = &g_kmap[(c + 1) * 64];
                float* Fb = Fbuf + ((c + 1) & 1) * FBUF_FLOATS;
                #pragma unroll
                for (int j = 0; j < 8; ++j) {
                    int k  = lane + 32 * (j & 1);
                    int n4 = 4 * (warp * 4 + (j >> 1));
                    unsigned km = kmp[k];
                    int u = km & 255, v = (km >> 8) & 255;
                    float4 val;
                    if (km & 0x10000u) {
                        const float4 a0 = *(const float4*)&xs1l[(0 * MUL1 + u) * XSTR + n4];
                        const float4 b0 = *(const float4*)&xs1l[(0 * MUL1 + v) * XSTR + n4];
                        const float4 a1 = *(const float4*)&xs1l[(1 * MUL1 + u) * XSTR + n4];
                        const float4 b1 = *(const float4*)&xs1l[(1 * MUL1 + v) * XSTR + n4];
                        const float4 a2 = *(const float4*)&xs1l[(2 * MUL1 + u) * XSTR + n4];
                        const float4 b2 = *(const float4*)&xs1l[(2 * MUL1 + v) * XSTR + n4];
                        val.x = a0.x * b0.x + a1.x * b1.x + a2.x * b2.x;
                        val.y = a0.y * b0.y + a1.y * b1.y + a2.y * b2.y;
                        val.z = a0.z * b0.z + a1.z * b1.z + a2.z * b2.z;
                        val.w = a0.w * b0.w + a1.w * b1.w + a2.w * b2.w;
                    } else {
                        const float4 a = *(const float4*)&xs0l[u * XSTR + n4];
                        const float4 bb = *(const float4*)&xs0l[v * XSTR + n4];
                        val.x = a.x * bb.x; val.y = a.y * bb.y;
                        val.z = a.z * bb.z; val.w = a.w * bb.w;
                    }
                    Fb[(n4 + 0) * FSTR + k] = to_tf32(val.x);
                    Fb[(n4 + 1) * FSTR + k] = to_tf32(val.y);
                    Fb[(n4 + 2) * FSTR + k] = to_tf32(val.z);
                    Fb[(n4 + 3) * FSTR + k] = to_tf32(val.w);
                }
            }
        } else {
            // ---- consumers: mma chunk c ----
            const float* Fb = Fbuf + (c & 1) * FBUF_FLOATS;
            const float* Wb = Wbuf + (c & 1) * WCHUNK_FLOATS;
            cp_wait0();    // own groups landed
            bar_cons();    // make ALL consumers' copies visible before reading
            #pragma unroll 2
            for (int ks = 0; ks < 8; ++ks) {
                const int k0 = 8 * ks;
                uint32_t a[2][4], bf[4][2];
                #pragma unroll
                for (int mt = 0; mt < 2; ++mt) {
                    int base = (32 * rg + 16 * mt + gy) * FSTR + k0 + gx;
                    a[mt][0] = fbits(Fb[base]);
                    a[mt][1] = fbits(Fb[base + 8 * FSTR]);
                    a[mt][2] = fbits(Fb[base + 4]);
                    a[mt][3] = fbits(Fb[base + 8 * FSTR + 4]);
                }
                #pragma unroll
                for (int nt = 0; nt < 4; ++nt) {
                    int bbase = (k0 + gx) * WSTR + 32 * cg + 8 * nt + gy;
                    bf[nt][0] = fbits(Wb[bbase]);
                    bf[nt][1] = fbits(Wb[bbase + 4 * WSTR]);
                }
                #pragma unroll
                for (int mt = 0; mt < 2; ++mt)
                    #pragma unroll
                    for (int nt = 0; nt < 4; ++nt)
                        mma_tf32(d1[mt][nt], a[mt], bf[nt]);
            }
            // prefetch weight chunk c+1
            if (c + 1 < NCH) {
                const char* src = (const char*)&g_WcB[(c + 1) * WCHUNK_FLOATS];
                uint32_t dst = w_s + ((c + 1) & 1) * WCHUNK_FLOATS * 4;
                #pragma unroll
                for (int j = 0; j < 5; ++j) {
                    int e = tc + 256 * j;
                    if (e < WCHUNK_FLOATS / 4) cp_async16(dst + e * 16, src + e * 16);
                }
                cp_commit();
            }
        }
        __syncthreads();
    }

    // ---- phase-1 epilogue (consumers): store out0; then prefetch W3[0] ----
    if (!prod) {
        #pragma unroll
        for (int mt = 0; mt < 2; ++mt) {
            #pragma unroll
            for (int nt = 0; nt < 4; ++nt) {
                int r = 32 * rg + 16 * mt + gy;
                int cc = 32 * cg + 8 * nt + 2 * gx;
                int gn = nbase + r;
                if (gn < nNodes)
                    *(float2*)&out[(size_t)gn * DIM + cc] = make_float2(d1[mt][nt][0], d1[mt][nt][1]);
                int gn2 = nbase + r + 8;
                if (gn2 < nNodes)
                    *(float2*)&out[(size_t)gn2 * DIM + cc] = make_float2(d1[mt][nt][2], d1[mt][nt][3]);
            }
        }
        const char* src = (const char*)&g_W3B[0];
        #pragma unroll
        for (int j = 0; j < 5; ++j) {
            int e = tc + 256 * j;
            if (e < WCHUNK_FLOATS / 4) cp_async16(w_s + e * 16, src + e * 16);
        }
        cp_commit();
    }

    // ================= phase 2: Y = x0 @ W3r; producers contract =================
    const int n2 = tc >> 1;    // producer node 0..127
    const int h  = tc & 1;     // w half
    float o[48];
    #pragma unroll
    for (int j = 0; j < 48; ++j) o[j] = 0.f;

    for (int ci = 0; ci < NCH2; ++ci) {
        if (!prod) {
            float* Yb = Fbuf + (ci & 1) * FBUF_FLOATS;
            const float* Wb = Wbuf + (ci & 1) * WCHUNK_FLOATS;
            cp_wait0();
            bar_cons();    // cross-consumer visibility of W3 chunk ci

            float d2[2][4][4];
            #pragma unroll
            for (int mt = 0; mt < 2; ++mt)
                #pragma unroll
                for (int nt = 0; nt < 4; ++nt)
                    #pragma unroll
                    for (int p = 0; p < 4; ++p) d2[mt][nt][p] = 0.f;

            #pragma unroll 2
            for (int ks = 0; ks < 8; ++ks) {
                const int k0 = 8 * ks;
                uint32_t a[2][4], bf[4][2];
                #pragma unroll
                for (int mt = 0; mt < 2; ++mt) {
                    int base = (32 * rg + 16 * mt + gy) * FSTR + k0 + gx;
                    a[mt][0] = fbits(x0r[base]);
                    a[mt][1] = fbits(x0r[base + 8 * FSTR]);
                    a[mt][2] = fbits(x0r[base + 4]);
                    a[mt][3] = fbits(x0r[base + 8 * FSTR + 4]);
                }
                #pragma unroll
                for (int nt = 0; nt < 4; ++nt) {
                    int bbase = (k0 + gx) * WSTR + 32 * cg + 8 * nt + gy;
                    bf[nt][0] = fbits(Wb[bbase]);
                    bf[nt][1] = fbits(Wb[bbase + 4 * WSTR]);
                }
                #pragma unroll
                for (int mt = 0; mt < 2; ++mt)
                    #pragma unroll
                    for (int nt = 0; nt < 4; ++nt)
                        mma_tf32(d2[mt][nt], a[mt], bf[nt]);
            }

            // store Y fragments
            #pragma unroll
            for (int mt = 0; mt < 2; ++mt) {
                #pragma unroll
                for (int nt = 0; nt < 4; ++nt) {
                    int r = 32 * rg + 16 * mt + gy;
                    int cc = 32 * cg + 8 * nt + 2 * gx;
                    *(float2*)&Yb[r * FSTR + cc]       = make_float2(d2[mt][nt][0], d2[mt][nt][1]);
                    *(float2*)&Yb[(r + 8) * FSTR + cc] = make_float2(d2[mt][nt][2], d2[mt][nt][3]);
                }
            }

            if (ci + 1 < NCH2) {
                const char* src = (const char*)&g_W3B[(ci + 1) * WCHUNK_FLOATS];
                uint32_t dst = w_s + ((ci + 1) & 1) * WCHUNK_FLOATS * 4;
                #pragma unroll
                for (int j = 0; j < 5; ++j) {
                    int e = tc + 256 * j;
                    if (e < WCHUNK_FLOATS / 4) cp_async16(dst + e * 16, src + e * 16);
                }
                cp_commit();
            }
        } else if (ci > 0) {
            // producers: contract Y chunk ci-1
            const float* Yb = Fbuf + ((ci - 1) & 1) * FBUF_FLOATS;
            #pragma unroll
            for (int ul = 0; ul < 2; ++ul) {
                int u = 2 * (ci - 1) + ul;
                float xi0 = xs1l[(0 * MUL1 + u) * XSTR + n2];
                float xi1 = xs1l[(1 * MUL1 + u) * XSTR + n2];
                float xi2 = xs1l[(2 * MUL1 + u) * XSTR + n2];
                #pragma unroll
                for (int q = 0; q < 4; ++q) {
                    float4 y = *(const float4*)&Yb[n2 * FSTR + ul * 32 + 16 * h + 4 * q];
                    float yv[4] = {y.x, y.y, y.z, y.w};
                    #pragma unroll
                    for (int e = 0; e < 4; ++e) {
                        int lw = 4 * q + e;
                        o[lw * 3 + 0] += yv[e] * xi0;
                        o[lw * 3 + 1] += yv[e] * xi1;
                        o[lw * 3 + 2] += yv[e] * xi2;
                    }
                }
            }
        }
        __syncthreads();
    }

    // final contraction (chunk 15) + out1 store, producers only
    if (prod) {
        const float* Yb = Fbuf + ((NCH2 - 1) & 1) * FBUF_FLOATS;
        #pragma unroll
        for (int ul = 0; ul < 2; ++ul) {
            int u = 2 * (NCH2 - 1) + ul;
            float xi0 = xs1l[(0 * MUL1 + u) * XSTR + n2];
            float xi1 = xs1l[(1 * MUL1 + u) * XSTR + n2];
            float xi2 = xs1l[(2 * MUL1 + u) * XSTR + n2];
            #pragma unroll
            for (int q = 0; q < 4; ++q) {
                float4 y = *(const float4*)&Yb[n2 * FSTR + ul * 32 + 16 * h + 4 * q];
                float yv[4] = {y.x, y.y, y.z, y.w};
                #pragma unroll
                for (int e = 0; e < 4; ++e) {
                    int lw = 4 * q + e;
                    o[lw * 3 + 0] += yv[e] * xi0;
                    o[lw * 3 + 1] += yv[e] * xi1;
                    o[lw * 3 + 2] += yv[e] * xi2;
                }
            }
        }
        int gn = nbase + n2;
        if (gn < nNodes) {
            float* dst = &out[(size_t)gn * DIM + MUL0 + 48 * h];
            #pragma unroll
            for (int j = 0; j < 12; ++j)
                *(float4*)&dst[4 * j] = make_float4(o[4 * j], o[4 * j + 1], o[4 * j + 2], o[4 * j + 3]);
        }
    }
}

// ---------------- launch ----------------
extern "C" void kernel_launch(void* const* d_in, const int* in_sizes, int n_in,
                              void* d_out, int out_size) {
    const float* A  = (const float*)d_in[0];
    const float* B  = (const float*)d_in[1];
    const float* W1 = (const float*)d_in[2];
    const float* W2 = (const float*)d_in[3];
    const float* W3 = (const float*)d_in[4];
    const float* W4 = (const float*)d_in[5];
    const float* W5 = (const float*)d_in[6];
    float* out = (float*)d_out;
    int nNodes = in_sizes[0] / DIM;

    cudaFuncSetAttribute(node_block_kernel,
                         cudaFuncAttributeMaxDynamicSharedMemorySize, SMEM_BYTES);

    prep_kernel<<<256, 256>>>(W1, W2, W3, W4, W5);
    int nb = (nNodes + TN - 1) / TN;
    node_block_kernel<<<nb, THREADS, SMEM_BYTES>>>(A, B, out, nNodes);
}